// round 1
// baseline (speedup 1.0000x reference)
#include <cuda_runtime.h>
#include <cstdint>

// ---------------- problem constants (fixed shapes from reference) ----------------
constexpr int MODAL  = 8;      // M (sequence / modal length)
constexpr int DMODEL = 1024;   // d_model
constexpr int NHEAD  = 16;
constexpr int DK     = 64;
constexpr int SEXT   = 64;     // external attention S
constexpr int BSZ    = 4096;
constexpr int ROWS   = BSZ * MODAL;   // 32768

// ---------------- scratch (device globals: allocation-free) ----------------
__device__ float g_q  [(size_t)ROWS * DMODEL];
__device__ float g_k  [(size_t)ROWS * DMODEL];
__device__ float g_v  [(size_t)ROWS * DMODEL];
__device__ float g_att[(size_t)ROWS * DMODEL];
__device__ float g_x  [(size_t)ROWS * DMODEL];
__device__ float g_scores[(size_t)BSZ * NHEAD * MODAL * MODAL];  // [b][h][m][n]
__device__ float g_xa [(size_t)ROWS * SEXT];
__device__ float g_a  [(size_t)ROWS * SEXT];
__device__ unsigned g_min_u;

// ---------------- float<->orderable-uint encoding for global atomic min ----------------
__device__ __forceinline__ unsigned enc_min(float f) {
    unsigned u = __float_as_uint(f);
    return (u & 0x80000000u) ? ~u : (u | 0x80000000u);
}
__device__ __forceinline__ float dec_min(unsigned k) {
    return (k & 0x80000000u) ? __uint_as_float(k ^ 0x80000000u)
                             : __uint_as_float(~k);
}

__global__ void init_min_kernel() { g_min_u = 0xFFFFFFFFu; }

// ---------------- tf32 helpers ----------------
__device__ __forceinline__ unsigned f2tf(float f) {
    unsigned r;
    asm("cvt.rna.tf32.f32 %0, %1;" : "=r"(r) : "f"(f));
    return r;
}

__device__ __forceinline__ void mma_tf32(float* c, const unsigned* a, const unsigned* b) {
    asm volatile(
        "mma.sync.aligned.m16n8k8.row.col.f32.tf32.tf32.f32 "
        "{%0,%1,%2,%3}, {%4,%5,%6,%7}, {%8,%9}, {%0,%1,%2,%3};\n"
        : "+f"(c[0]), "+f"(c[1]), "+f"(c[2]), "+f"(c[3])
        : "r"(a[0]), "r"(a[1]), "r"(a[2]), "r"(a[3]),
          "r"(b[0]), "r"(b[1]));
}

// ---------------- NT GEMM: C[M,N] = A[M,K] * B[N,K]^T (+ Res) ----------------
// A, B row-major, K-contiguous. tf32 mma, fp32 accumulate.
template<int BM, int BN, bool RES>
__global__ void __launch_bounds__(256, 1) gemm_nt(
    const float* __restrict__ A, const float* __restrict__ B,
    const float* __restrict__ Res, float* __restrict__ C,
    int M, int N, int K)
{
    constexpr int BK = 32;
    __shared__ unsigned As[BK][BM + 8];
    __shared__ unsigned Bs[BK][BN + 8];

    const int tid = threadIdx.x;
    const int lane = tid & 31;
    const int wid = tid >> 5;
    const int wm = wid & 3;       // 4 warps along M
    const int wn = wid >> 2;      // 2 warps along N
    constexpr int WMT = BM / 4;   // warp tile M (32)
    constexpr int WNT = BN / 2;   // warp tile N (64 or 32)
    constexpr int MT = WMT / 16;  // 2
    constexpr int NT = WNT / 8;   // 8 or 4
    const int bm = blockIdx.y * BM;
    const int bn = blockIdx.x * BN;

    constexpr int APER = BM * BK / (4 * 256);
    constexpr int BPER = BN * BK / (4 * 256);
    float4 areg[APER], breg[BPER];
    float acc[MT][NT][4];
#pragma unroll
    for (int i = 0; i < MT; i++)
#pragma unroll
        for (int j = 0; j < NT; j++)
#pragma unroll
            for (int t = 0; t < 4; t++) acc[i][j][t] = 0.f;

    const int nk = K / BK;

    // initial global loads
#pragma unroll
    for (int i = 0; i < APER; i++) {
        int id = tid + 256 * i; int r = id >> 3, c4 = id & 7;
        areg[i] = *(const float4*)&A[(size_t)(bm + r) * K + c4 * 4];
    }
#pragma unroll
    for (int i = 0; i < BPER; i++) {
        int id = tid + 256 * i; int r = id >> 3, c4 = id & 7;
        breg[i] = *(const float4*)&B[(size_t)(bn + r) * K + c4 * 4];
    }

    for (int kt = 0; kt < nk; kt++) {
        // stage registers -> smem (transposed, tf32-converted)
#pragma unroll
        for (int i = 0; i < APER; i++) {
            int id = tid + 256 * i; int r = id >> 3, c = (id & 7) * 4;
            As[c + 0][r] = f2tf(areg[i].x); As[c + 1][r] = f2tf(areg[i].y);
            As[c + 2][r] = f2tf(areg[i].z); As[c + 3][r] = f2tf(areg[i].w);
        }
#pragma unroll
        for (int i = 0; i < BPER; i++) {
            int id = tid + 256 * i; int r = id >> 3, c = (id & 7) * 4;
            Bs[c + 0][r] = f2tf(breg[i].x); Bs[c + 1][r] = f2tf(breg[i].y);
            Bs[c + 2][r] = f2tf(breg[i].z); Bs[c + 3][r] = f2tf(breg[i].w);
        }
        __syncthreads();

        // prefetch next K-chunk
        if (kt + 1 < nk) {
            int ko = (kt + 1) * BK;
#pragma unroll
            for (int i = 0; i < APER; i++) {
                int id = tid + 256 * i; int r = id >> 3, c4 = id & 7;
                areg[i] = *(const float4*)&A[(size_t)(bm + r) * K + ko + c4 * 4];
            }
#pragma unroll
            for (int i = 0; i < BPER; i++) {
                int id = tid + 256 * i; int r = id >> 3, c4 = id & 7;
                breg[i] = *(const float4*)&B[(size_t)(bn + r) * K + ko + c4 * 4];
            }
        }

        // compute: 4 k-steps of k=8
#pragma unroll
        for (int ks = 0; ks < 4; ks++) {
            const int k0 = ks * 8;
            unsigned af[MT][4], bf[NT][2];
#pragma unroll
            for (int i = 0; i < MT; i++) {
                int m0 = wm * WMT + i * 16 + (lane >> 2);
                int kk = k0 + (lane & 3);
                af[i][0] = As[kk][m0];
                af[i][1] = As[kk][m0 + 8];
                af[i][2] = As[kk + 4][m0];
                af[i][3] = As[kk + 4][m0 + 8];
            }
#pragma unroll
            for (int j = 0; j < NT; j++) {
                int n0 = wn * WNT + j * 8 + (lane >> 2);
                int kk = k0 + (lane & 3);
                bf[j][0] = Bs[kk][n0];
                bf[j][1] = Bs[kk + 4][n0];
            }
#pragma unroll
            for (int i = 0; i < MT; i++)
#pragma unroll
                for (int j = 0; j < NT; j++)
                    mma_tf32(acc[i][j], af[i], bf[j]);
        }
        __syncthreads();
    }

    // epilogue
#pragma unroll
    for (int i = 0; i < MT; i++) {
#pragma unroll
        for (int j = 0; j < NT; j++) {
            int r0 = bm + wm * WMT + i * 16 + (lane >> 2);
            int c0 = bn + wn * WNT + j * 8 + (lane & 3) * 2;
            float2 v0 = make_float2(acc[i][j][0], acc[i][j][1]);
            float2 v1 = make_float2(acc[i][j][2], acc[i][j][3]);
            if (RES) {
                float2 ra = *(const float2*)&Res[(size_t)r0 * N + c0];
                float2 rb = *(const float2*)&Res[(size_t)(r0 + 8) * N + c0];
                v0.x += ra.x; v0.y += ra.y;
                v1.x += rb.x; v1.y += rb.y;
            }
            *(float2*)&C[(size_t)r0 * N + c0] = v0;
            *(float2*)&C[(size_t)(r0 + 8) * N + c0] = v1;
        }
    }
}

// ---------------- attention pass A: scores + global min ----------------
constexpr int QPAD = DMODEL + 4;  // 1028, conflict-avoiding row stride

extern __shared__ float dynsmem[];

__global__ void __launch_bounds__(256) attn_scores_kernel() {
    float* qs = dynsmem;                       // [8][1028]
    float* ks = dynsmem + MODAL * QPAD;        // [8][1028]
    const int b = blockIdx.x, tid = threadIdx.x;
    const float4* qg = (const float4*)(g_q + (size_t)b * MODAL * DMODEL);
    const float4* kg = (const float4*)(g_k + (size_t)b * MODAL * DMODEL);
    for (int i = tid; i < MODAL * DMODEL / 4; i += 256) {
        int m = i >> 8, c = i & 255;
        *(float4*)&qs[m * QPAD + c * 4] = qg[i];
        *(float4*)&ks[m * QPAD + c * 4] = kg[i];
    }
    __syncthreads();

    float lmin = 3.4e38f;
    for (int s = tid; s < NHEAD * MODAL * MODAL; s += 256) {
        int h = s >> 6, m = (s >> 3) & 7, n = s & 7;
        const float4* qr = (const float4*)&qs[m * QPAD + h * DK];
        const float4* kr = (const float4*)&ks[n * QPAD + h * DK];
        float acc = 0.f;
#pragma unroll
        for (int d = 0; d < 16; d++) {
            float4 a = qr[d], c = kr[d];
            acc += a.x * c.x + a.y * c.y + a.z * c.z + a.w * c.w;
        }
        acc *= 0.125f;  // 1/sqrt(DK)
        g_scores[(size_t)b * 1024 + s] = acc;
        lmin = fminf(lmin, acc);
    }
    // block min reduce
#pragma unroll
    for (int o = 16; o; o >>= 1) lmin = fminf(lmin, __shfl_xor_sync(0xffffffffu, lmin, o));
    __shared__ float wmn[8];
    if ((tid & 31) == 0) wmn[tid >> 5] = lmin;
    __syncthreads();
    if (tid == 0) {
        float m = wmn[0];
#pragma unroll
        for (int i = 1; i < 8; i++) m = fminf(m, wmn[i]);
        atomicMin(&g_min_u, enc_min(m));
    }
}

// ---------------- attention pass B: scale / L2-norm / softmax / out = attn @ V ----------------
__global__ void __launch_bounds__(256) attn_out_kernel() {
    __shared__ float vs[MODAL * QPAD];     // 8 x 1028
    __shared__ float sc[NHEAD * 64];       // scaled scores [h][m][n]
    __shared__ float aw[NHEAD * 64];       // attention weights
    const int b = blockIdx.x, tid = threadIdx.x;
    const float inv = 1.f / fabsf(dec_min(g_min_u));

    const float4* vg = (const float4*)(g_v + (size_t)b * MODAL * DMODEL);
    for (int i = tid; i < MODAL * DMODEL / 4; i += 256) {
        int m = i >> 8, c = i & 255;
        *(float4*)&vs[m * QPAD + c * 4] = vg[i];
    }
    for (int i = tid; i < 1024; i += 256)
        sc[i] = g_scores[(size_t)b * 1024 + i] * inv;
    __syncthreads();

    if (tid < 128) {
        int h = tid >> 3, m = tid & 7;
        float r[8]; float ss = 0.f;
#pragma unroll
        for (int n = 0; n < 8; n++) { r[n] = sc[h * 64 + m * 8 + n]; ss += r[n] * r[n]; }
        float nrm = fmaxf(sqrtf(ss), 1e-12f);
        float rn = 1.f / nrm;
        float mx = -3.4e38f;
#pragma unroll
        for (int n = 0; n < 8; n++) { r[n] *= rn; mx = fmaxf(mx, r[n]); }
        float sum = 0.f;
#pragma unroll
        for (int n = 0; n < 8; n++) { r[n] = expf(r[n] - mx); sum += r[n]; }
        float is = 1.f / sum;
#pragma unroll
        for (int n = 0; n < 8; n++) aw[h * 64 + m * 8 + n] = r[n] * is;
    }
    __syncthreads();

    float* og = g_att + (size_t)b * MODAL * DMODEL;
    for (int o = tid; o < MODAL * DMODEL; o += 256) {
        int m = o >> 10, col = o & 1023, h = col >> 6;
        float acc = 0.f;
#pragma unroll
        for (int n = 0; n < 8; n++) acc += aw[h * 64 + m * 8 + n] * vs[n * QPAD + col];
        og[o] = acc;
    }
}

// ---------------- LayerNorm (biased var, eps=1e-10) ----------------
__global__ void __launch_bounds__(256) ln_kernel(
    const float* __restrict__ gamma, const float* __restrict__ beta,
    float* __restrict__ out)
{
    const int wid = threadIdx.x >> 5, lane = threadIdx.x & 31;
    const size_t row = (size_t)blockIdx.x * 8 + wid;
    const float4* xr = (const float4*)(g_x + row * DMODEL);
    float4 v[8];
    float s = 0.f, s2 = 0.f;
#pragma unroll
    for (int i = 0; i < 8; i++) {
        v[i] = xr[lane + 32 * i];
        s += v[i].x + v[i].y + v[i].z + v[i].w;
        s2 += v[i].x * v[i].x + v[i].y * v[i].y + v[i].z * v[i].z + v[i].w * v[i].w;
    }
#pragma unroll
    for (int o = 16; o; o >>= 1) {
        s += __shfl_xor_sync(0xffffffffu, s, o);
        s2 += __shfl_xor_sync(0xffffffffu, s2, o);
    }
    const float mu = s * (1.f / DMODEL);
    const float var = fmaxf(s2 * (1.f / DMODEL) - mu * mu, 0.f);
    const float rs = rsqrtf(var + 1e-10f);
    float4* orow = (float4*)(out + row * DMODEL);
    const float4* gm = (const float4*)gamma;
    const float4* bt = (const float4*)beta;
#pragma unroll
    for (int i = 0; i < 8; i++) {
        int c4 = lane + 32 * i;
        float4 g = gm[c4], bb = bt[c4], x = v[i], r;
        r.x = (x.x - mu) * rs * g.x + bb.x;
        r.y = (x.y - mu) * rs * g.y + bb.y;
        r.z = (x.z - mu) * rs * g.z + bb.z;
        r.w = (x.w - mu) * rs * g.w + bb.w;
        orow[c4] = r;
    }
}

// ---------------- ExternalAttention normalization ----------------
// a = softmax over modal axis (M=8), then a /= sum over S per (b,m)
__global__ void __launch_bounds__(64) ext_norm_kernel() {
    const int b = blockIdx.x, s = threadIdx.x;
    __shared__ float sm[MODAL][SEXT];
    __shared__ float rsum[MODAL];
    float xv[MODAL];
    float mx = -3.4e38f;
#pragma unroll
    for (int m = 0; m < MODAL; m++) {
        xv[m] = g_xa[((size_t)b * MODAL + m) * SEXT + s];
        mx = fmaxf(mx, xv[m]);
    }
    float sum = 0.f;
#pragma unroll
    for (int m = 0; m < MODAL; m++) { xv[m] = expf(xv[m] - mx); sum += xv[m]; }
    const float is = 1.f / sum;
#pragma unroll
    for (int m = 0; m < MODAL; m++) sm[m][s] = xv[m] * is;
    __syncthreads();
    if (s < MODAL) {
        float t = 0.f;
        for (int j = 0; j < SEXT; j++) t += sm[s][j];
        rsum[s] = 1.f / t;
    }
    __syncthreads();
#pragma unroll
    for (int m = 0; m < MODAL; m++)
        g_a[((size_t)b * MODAL + m) * SEXT + s] = sm[m][s] * rsum[m];
}

// ---------------- launch ----------------
extern "C" void kernel_launch(void* const* d_in, const int* in_sizes, int n_in,
                              void* d_out, int out_size)
{
    const float* q     = (const float*)d_in[0];
    const float* k     = (const float*)d_in[1];
    const float* v     = (const float*)d_in[2];
    const float* Wq    = (const float*)d_in[3];
    const float* Wk    = (const float*)d_in[4];
    const float* Wv    = (const float*)d_in[5];
    const float* Wfc   = (const float*)d_in[6];
    const float* gamma = (const float*)d_in[7];
    const float* beta  = (const float*)d_in[8];
    const float* Wmk   = (const float*)d_in[9];
    const float* Wmv   = (const float*)d_in[10];
    float* out = (float*)d_out;

    float *pq, *pk, *pv, *patt, *px, *pxa, *pa;
    cudaGetSymbolAddress((void**)&pq,   g_q);
    cudaGetSymbolAddress((void**)&pk,   g_k);
    cudaGetSymbolAddress((void**)&pv,   g_v);
    cudaGetSymbolAddress((void**)&patt, g_att);
    cudaGetSymbolAddress((void**)&px,   g_x);
    cudaGetSymbolAddress((void**)&pxa,  g_xa);
    cudaGetSymbolAddress((void**)&pa,   g_a);

    const int smem_sc = 2 * MODAL * QPAD * (int)sizeof(float);  // 65792 B
    cudaFuncSetAttribute(attn_scores_kernel,
                         cudaFuncAttributeMaxDynamicSharedMemorySize, smem_sc);

    init_min_kernel<<<1, 1>>>();

    dim3 g1(DMODEL / 128, ROWS / 128);  // (8, 256)
    gemm_nt<128, 128, false><<<g1, 256>>>(q, Wq, nullptr, pq, ROWS, DMODEL, DMODEL);
    gemm_nt<128, 128, false><<<g1, 256>>>(k, Wk, nullptr, pk, ROWS, DMODEL, DMODEL);
    gemm_nt<128, 128, false><<<g1, 256>>>(v, Wv, nullptr, pv, ROWS, DMODEL, DMODEL);

    attn_scores_kernel<<<BSZ, 256, smem_sc>>>();
    attn_out_kernel<<<BSZ, 256>>>();

    // x = attn_out @ Wfc^T + q (residual)
    gemm_nt<128, 128, true><<<g1, 256>>>(patt, Wfc, q, px, ROWS, DMODEL, DMODEL);

    // LayerNorm -> d_out (this is 'x' for external attention)
    ln_kernel<<<ROWS / 8, 256>>>(gamma, beta, out);

    // xa = x @ Wmk^T  (N=64)
    gemm_nt<128, 64, false><<<dim3(1, ROWS / 128), 256>>>(out, Wmk, nullptr, pxa,
                                                          ROWS, SEXT, DMODEL);
    // softmax over modal axis + renorm over S
    ext_norm_kernel<<<BSZ, 64>>>();

    // out = x + a @ Wmv^T  (K=64, in-place elementwise residual on d_out)
    gemm_nt<128, 128, true><<<dim3(DMODEL / 128, ROWS / 128), 256>>>(pa, Wmv, out, out,
                                                                     ROWS, DMODEL, SEXT);
}

// round 3
// speedup vs baseline: 1.9440x; 1.9440x over previous
#include <cuda_runtime.h>
#include <cstdint>

// ---------------- problem constants (fixed shapes from reference) ----------------
constexpr int MODAL  = 8;      // M (sequence / modal length)
constexpr int DMODEL = 1024;   // d_model
constexpr int NHEAD  = 16;
constexpr int DK     = 64;
constexpr int SEXT   = 64;     // external attention S
constexpr int BSZ    = 4096;
constexpr int ROWS   = BSZ * MODAL;   // 32768

// ---------------- scratch (device globals: allocation-free) ----------------
__device__ float g_q  [(size_t)ROWS * DMODEL];
__device__ float g_k  [(size_t)ROWS * DMODEL];
__device__ float g_v  [(size_t)ROWS * DMODEL];
__device__ float g_att[(size_t)ROWS * DMODEL];
__device__ float g_x  [(size_t)ROWS * DMODEL];
__device__ float g_scores[(size_t)BSZ * NHEAD * MODAL * MODAL];  // [b][h][m][n]
__device__ float g_xa [(size_t)ROWS * SEXT];
__device__ float g_a  [(size_t)ROWS * SEXT];
__device__ unsigned g_min_u;

// ---------------- float<->orderable-uint encoding for global atomic min ----------------
__device__ __forceinline__ unsigned enc_min(float f) {
    unsigned u = __float_as_uint(f);
    return (u & 0x80000000u) ? ~u : (u | 0x80000000u);
}
__device__ __forceinline__ float dec_min(unsigned k) {
    return (k & 0x80000000u) ? __uint_as_float(k ^ 0x80000000u)
                             : __uint_as_float(~k);
}

__global__ void init_min_kernel() { g_min_u = 0xFFFFFFFFu; }

// ---------------- tf32 helpers ----------------
__device__ __forceinline__ unsigned f2tf(float f) {
    unsigned r;
    asm("cvt.rna.tf32.f32 %0, %1;" : "=r"(r) : "f"(f));
    return r;
}

__device__ __forceinline__ void mma_tf32(float* c, const unsigned* a, const unsigned* b) {
    asm volatile(
        "mma.sync.aligned.m16n8k8.row.col.f32.tf32.tf32.f32 "
        "{%0,%1,%2,%3}, {%4,%5,%6,%7}, {%8,%9}, {%0,%1,%2,%3};\n"
        : "+f"(c[0]), "+f"(c[1]), "+f"(c[2]), "+f"(c[3])
        : "r"(a[0]), "r"(a[1]), "r"(a[2]), "r"(a[3]),
          "r"(b[0]), "r"(b[1]));
}

__device__ __forceinline__ uint32_t smem_u32(const void* p) {
    uint32_t a;
    asm("{ .reg .u64 t; cvta.to.shared.u64 t, %1; cvt.u32.u64 %0, t; }" : "=r"(a) : "l"(p));
    return a;
}
__device__ __forceinline__ void cp16(uint32_t dst, const void* src) {
    asm volatile("cp.async.cg.shared.global [%0], [%1], 16;" :: "r"(dst), "l"(src));
}
#define CP_COMMIT() asm volatile("cp.async.commit_group;" ::: "memory")
#define CP_WAIT2()  asm volatile("cp.async.wait_group 2;" ::: "memory")

// =====================================================================
// NT GEMM via cp.async + swizzled k-major smem + tf32 HMMA.
// C[M,N] = A[M,K] * B[N,K]^T (+ Res). BM=128, BK=32, BN in {128,64}.
// smem layout per stage: A[128][32] then B[BN][32], each word at
//   word(m,kk) = m*32 + (((kk>>2) ^ (m&7)) << 2) + (kk&3)
// -> cp.async 16B stores AND all mma fragment loads are bank-conflict-free.
// 3-stage cp.async pipeline; rounding to tf32 happens on the read side.
// =====================================================================
template<int BN, bool RES>
__global__ void __launch_bounds__(256, 2) gemm_ca(
    const float* __restrict__ A, const float* __restrict__ B,
    const float* __restrict__ Res, float* __restrict__ C, int K, int N)
{
    constexpr int AW = 128 * 32;          // words per A stage
    constexpr int BW = BN * 32;           // words per B stage
    constexpr int STW = AW + BW;          // words per stage
    constexpr int BCH = BN * 8 / 256;     // B chunks per thread (4 or 2)
    constexpr int WNT = BN / 2;           // warp tile N (64 or 32)
    constexpr int NT  = WNT / 8;          // 8 or 4
    constexpr int MT  = 2;                // warp tile M = 32

    extern __shared__ float smf[];
    const uint32_t sbase = smem_u32(smf);

    const int tid  = threadIdx.x;
    const int lane = tid & 31;
    const int wid  = tid >> 5;
    const int wm   = wid & 3;             // 4 warps along M
    const int wn   = wid >> 2;            // 2 warps along N
    const int bm   = blockIdx.y * 128;
    const int bn   = blockIdx.x * BN;

    const int mA = tid >> 3;              // 0..31 (+32 per iter)
    const int cA = tid & 7;               // 16B chunk within 128B row
    const int nk = K / 32;

    // ---- cp.async issue for one k-tile into stage s ----
    auto issue = [&](int kt, int s) {
        const uint32_t so = (uint32_t)s * STW * 4u;
        const int k0 = kt * 32;
#pragma unroll
        for (int i = 0; i < 4; i++) {
            const int m = mA + 32 * i;
            const uint32_t dst = sbase + so + (uint32_t)m * 128u + (uint32_t)((cA ^ (m & 7)) << 4);
            cp16(dst, A + (size_t)(bm + m) * K + k0 + cA * 4);
        }
#pragma unroll
        for (int i = 0; i < BCH; i++) {
            const int m = mA + 32 * i;
            const uint32_t dst = sbase + so + (uint32_t)AW * 4u
                               + (uint32_t)m * 128u + (uint32_t)((cA ^ (m & 7)) << 4);
            cp16(dst, B + (size_t)(bn + m) * K + k0 + cA * 4);
        }
    };

    float acc[MT][NT][4];
#pragma unroll
    for (int i = 0; i < MT; i++)
#pragma unroll
        for (int j = 0; j < NT; j++)
#pragma unroll
            for (int t = 0; t < 4; t++) acc[i][j][t] = 0.f;

    // preload stages 0,1
    issue(0, 0); CP_COMMIT();
    issue(1, 1); CP_COMMIT();

    const int kkl = lane & 3;
    const int mrow[MT] = { wm * 32 + 0 * 16 + (lane >> 2), wm * 32 + 1 * 16 + (lane >> 2) };
    int nrow[NT];
#pragma unroll
    for (int j = 0; j < NT; j++) nrow[j] = wn * WNT + j * 8 + (lane >> 2);

    for (int kt = 0; kt < nk; kt++) {
        const int s = kt % 3;
        if (kt + 2 < nk) issue(kt + 2, (kt + 2) % 3);
        CP_COMMIT();
        CP_WAIT2();
        __syncthreads();

        const float* as = smf + s * STW;
        const float* bs = as + AW;

#pragma unroll
        for (int ks = 0; ks < 4; ks++) {
            const int ch = ks * 2;        // (ks*8)>>2
            unsigned af[MT][4], bf[NT][2];
#pragma unroll
            for (int i = 0; i < MT; i++) {
                const int m0 = mrow[i];
                const int msw = m0 & 7;
                const int w0 = m0 * 32 + ((ch ^ msw) << 2) + kkl;
                const int w2 = m0 * 32 + (((ch + 1) ^ msw) << 2) + kkl;
                af[i][0] = f2tf(as[w0]);
                af[i][1] = f2tf(as[w0 + 256]);   // +8 rows
                af[i][2] = f2tf(as[w2]);
                af[i][3] = f2tf(as[w2 + 256]);
            }
#pragma unroll
            for (int j = 0; j < NT; j++) {
                const int n0 = nrow[j];
                const int nsw = n0 & 7;
                bf[j][0] = f2tf(bs[n0 * 32 + ((ch ^ nsw) << 2) + kkl]);
                bf[j][1] = f2tf(bs[n0 * 32 + (((ch + 1) ^ nsw) << 2) + kkl]);
            }
#pragma unroll
            for (int i = 0; i < MT; i++)
#pragma unroll
                for (int j = 0; j < NT; j++)
                    mma_tf32(acc[i][j], af[i], bf[j]);
        }
        __syncthreads();
    }

    // epilogue
#pragma unroll
    for (int i = 0; i < MT; i++) {
#pragma unroll
        for (int j = 0; j < NT; j++) {
            const int r0 = bm + wm * 32 + i * 16 + (lane >> 2);
            const int c0 = bn + wn * WNT + j * 8 + (lane & 3) * 2;
            float2 v0 = make_float2(acc[i][j][0], acc[i][j][1]);
            float2 v1 = make_float2(acc[i][j][2], acc[i][j][3]);
            if (RES) {
                float2 ra = *(const float2*)&Res[(size_t)r0 * N + c0];
                float2 rb = *(const float2*)&Res[(size_t)(r0 + 8) * N + c0];
                v0.x += ra.x; v0.y += ra.y;
                v1.x += rb.x; v1.y += rb.y;
            }
            *(float2*)&C[(size_t)r0 * N + c0] = v0;
            *(float2*)&C[(size_t)(r0 + 8) * N + c0] = v1;
        }
    }
}

// ---------------- attention pass A: scores + global min ----------------
constexpr int QPAD = DMODEL + 4;  // 1028, conflict-avoiding row stride

extern __shared__ float dynsmem[];

__global__ void __launch_bounds__(256) attn_scores_kernel() {
    float* qs = dynsmem;                       // [8][1028]
    float* ks = dynsmem + MODAL * QPAD;        // [8][1028]
    const int b = blockIdx.x, tid = threadIdx.x;
    const float4* qg = (const float4*)(g_q + (size_t)b * MODAL * DMODEL);
    const float4* kg = (const float4*)(g_k + (size_t)b * MODAL * DMODEL);
    for (int i = tid; i < MODAL * DMODEL / 4; i += 256) {
        int m = i >> 8, c = i & 255;
        *(float4*)&qs[m * QPAD + c * 4] = qg[i];
        *(float4*)&ks[m * QPAD + c * 4] = kg[i];
    }
    __syncthreads();

    float lmin = 3.4e38f;
    for (int s = tid; s < NHEAD * MODAL * MODAL; s += 256) {
        int h = s >> 6, m = (s >> 3) & 7, n = s & 7;
        const float4* qr = (const float4*)&qs[m * QPAD + h * DK];
        const float4* kr = (const float4*)&ks[n * QPAD + h * DK];
        float acc = 0.f;
#pragma unroll
        for (int d = 0; d < 16; d++) {
            float4 a = qr[d], c = kr[d];
            acc += a.x * c.x + a.y * c.y + a.z * c.z + a.w * c.w;
        }
        acc *= 0.125f;  // 1/sqrt(DK)
        g_scores[(size_t)b * 1024 + s] = acc;
        lmin = fminf(lmin, acc);
    }
#pragma unroll
    for (int o = 16; o; o >>= 1) lmin = fminf(lmin, __shfl_xor_sync(0xffffffffu, lmin, o));
    __shared__ float wmn[8];
    if ((tid & 31) == 0) wmn[tid >> 5] = lmin;
    __syncthreads();
    if (tid == 0) {
        float m = wmn[0];
#pragma unroll
        for (int i = 1; i < 8; i++) m = fminf(m, wmn[i]);
        atomicMin(&g_min_u, enc_min(m));
    }
}

// ---------------- attention pass B ----------------
__global__ void __launch_bounds__(256) attn_out_kernel() {
    __shared__ float vs[MODAL * QPAD];
    __shared__ float sc[NHEAD * 64];
    __shared__ float aw[NHEAD * 64];
    const int b = blockIdx.x, tid = threadIdx.x;
    const float inv = 1.f / fabsf(dec_min(g_min_u));

    const float4* vg = (const float4*)(g_v + (size_t)b * MODAL * DMODEL);
    for (int i = tid; i < MODAL * DMODEL / 4; i += 256) {
        int m = i >> 8, c = i & 255;
        *(float4*)&vs[m * QPAD + c * 4] = vg[i];
    }
    for (int i = tid; i < 1024; i += 256)
        sc[i] = g_scores[(size_t)b * 1024 + i] * inv;
    __syncthreads();

    if (tid < 128) {
        int h = tid >> 3, m = tid & 7;
        float r[8]; float ss = 0.f;
#pragma unroll
        for (int n = 0; n < 8; n++) { r[n] = sc[h * 64 + m * 8 + n]; ss += r[n] * r[n]; }
        float nrm = fmaxf(sqrtf(ss), 1e-12f);
        float rn = 1.f / nrm;
        float mx = -3.4e38f;
#pragma unroll
        for (int n = 0; n < 8; n++) { r[n] *= rn; mx = fmaxf(mx, r[n]); }
        float sum = 0.f;
#pragma unroll
        for (int n = 0; n < 8; n++) { r[n] = expf(r[n] - mx); sum += r[n]; }
        float is = 1.f / sum;
#pragma unroll
        for (int n = 0; n < 8; n++) aw[h * 64 + m * 8 + n] = r[n] * is;
    }
    __syncthreads();

    float* og = g_att + (size_t)b * MODAL * DMODEL;
    for (int o = tid; o < MODAL * DMODEL; o += 256) {
        int m = o >> 10, col = o & 1023, h = col >> 6;
        float acc = 0.f;
#pragma unroll
        for (int n = 0; n < 8; n++) acc += aw[h * 64 + m * 8 + n] * vs[n * QPAD + col];
        og[o] = acc;
    }
}

// ---------------- LayerNorm (biased var, eps=1e-10) ----------------
__global__ void __launch_bounds__(256) ln_kernel(
    const float* __restrict__ gamma, const float* __restrict__ beta,
    float* __restrict__ out)
{
    const int wid = threadIdx.x >> 5, lane = threadIdx.x & 31;
    const size_t row = (size_t)blockIdx.x * 8 + wid;
    const float4* xr = (const float4*)(g_x + row * DMODEL);
    float4 v[8];
    float s = 0.f, s2 = 0.f;
#pragma unroll
    for (int i = 0; i < 8; i++) {
        v[i] = xr[lane + 32 * i];
        s += v[i].x + v[i].y + v[i].z + v[i].w;
        s2 += v[i].x * v[i].x + v[i].y * v[i].y + v[i].z * v[i].z + v[i].w * v[i].w;
    }
#pragma unroll
    for (int o = 16; o; o >>= 1) {
        s += __shfl_xor_sync(0xffffffffu, s, o);
        s2 += __shfl_xor_sync(0xffffffffu, s2, o);
    }
    const float mu = s * (1.f / DMODEL);
    const float var = fmaxf(s2 * (1.f / DMODEL) - mu * mu, 0.f);
    const float rs = rsqrtf(var + 1e-10f);
    float4* orow = (float4*)(out + row * DMODEL);
    const float4* gm = (const float4*)gamma;
    const float4* bt = (const float4*)beta;
#pragma unroll
    for (int i = 0; i < 8; i++) {
        int c4 = lane + 32 * i;
        float4 g = gm[c4], bb = bt[c4], x = v[i], r;
        r.x = (x.x - mu) * rs * g.x + bb.x;
        r.y = (x.y - mu) * rs * g.y + bb.y;
        r.z = (x.z - mu) * rs * g.z + bb.z;
        r.w = (x.w - mu) * rs * g.w + bb.w;
        orow[c4] = r;
    }
}

// ---------------- ExternalAttention normalization ----------------
__global__ void __launch_bounds__(64) ext_norm_kernel() {
    const int b = blockIdx.x, s = threadIdx.x;
    __shared__ float sm[MODAL][SEXT];
    __shared__ float rsum[MODAL];
    float xv[MODAL];
    float mx = -3.4e38f;
#pragma unroll
    for (int m = 0; m < MODAL; m++) {
        xv[m] = g_xa[((size_t)b * MODAL + m) * SEXT + s];
        mx = fmaxf(mx, xv[m]);
    }
    float sum = 0.f;
#pragma unroll
    for (int m = 0; m < MODAL; m++) { xv[m] = expf(xv[m] - mx); sum += xv[m]; }
    const float is = 1.f / sum;
#pragma unroll
    for (int m = 0; m < MODAL; m++) sm[m][s] = xv[m] * is;
    __syncthreads();
    if (s < MODAL) {
        float t = 0.f;
        for (int j = 0; j < SEXT; j++) t += sm[s][j];
        rsum[s] = 1.f / t;
    }
    __syncthreads();
#pragma unroll
    for (int m = 0; m < MODAL; m++)
        g_a[((size_t)b * MODAL + m) * SEXT + s] = sm[m][s] * rsum[m];
}

// ---------------- launch ----------------
extern "C" void kernel_launch(void* const* d_in, const int* in_sizes, int n_in,
                              void* d_out, int out_size)
{
    const float* q     = (const float*)d_in[0];
    const float* k     = (const float*)d_in[1];
    const float* v     = (const float*)d_in[2];
    const float* Wq    = (const float*)d_in[3];
    const float* Wk    = (const float*)d_in[4];
    const float* Wv    = (const float*)d_in[5];
    const float* Wfc   = (const float*)d_in[6];
    const float* gamma = (const float*)d_in[7];
    const float* beta  = (const float*)d_in[8];
    const float* Wmk   = (const float*)d_in[9];
    const float* Wmv   = (const float*)d_in[10];
    float* out = (float*)d_out;

    float *pq, *pk, *pv, *patt, *px, *pxa, *pa;
    cudaGetSymbolAddress((void**)&pq,   g_q);
    cudaGetSymbolAddress((void**)&pk,   g_k);
    cudaGetSymbolAddress((void**)&pv,   g_v);
    cudaGetSymbolAddress((void**)&patt, g_att);
    cudaGetSymbolAddress((void**)&px,   g_x);
    cudaGetSymbolAddress((void**)&pxa,  g_xa);
    cudaGetSymbolAddress((void**)&pa,   g_a);

    const int smem_sc = 2 * MODAL * QPAD * (int)sizeof(float);
    cudaFuncSetAttribute(attn_scores_kernel,
                         cudaFuncAttributeMaxDynamicSharedMemorySize, smem_sc);

    const int smem128 = 3 * (128 * 32 + 128 * 32) * (int)sizeof(float);  // 98304
    const int smem64  = 3 * (128 * 32 + 64 * 32) * (int)sizeof(float);   // 73728
    cudaFuncSetAttribute(gemm_ca<128, false>,
                         cudaFuncAttributeMaxDynamicSharedMemorySize, smem128);
    cudaFuncSetAttribute(gemm_ca<128, true>,
                         cudaFuncAttributeMaxDynamicSharedMemorySize, smem128);
    cudaFuncSetAttribute(gemm_ca<64, false>,
                         cudaFuncAttributeMaxDynamicSharedMemorySize, smem64);

    init_min_kernel<<<1, 1>>>();

    dim3 g1(DMODEL / 128, ROWS / 128);  // (8, 256)
    gemm_ca<128, false><<<g1, 256, smem128>>>(q, Wq, nullptr, pq, DMODEL, DMODEL);
    gemm_ca<128, false><<<g1, 256, smem128>>>(k, Wk, nullptr, pk, DMODEL, DMODEL);
    gemm_ca<128, false><<<g1, 256, smem128>>>(v, Wv, nullptr, pv, DMODEL, DMODEL);

    attn_scores_kernel<<<BSZ, 256, smem_sc>>>();
    attn_out_kernel<<<BSZ, 256>>>();

    // x = attn_out @ Wfc^T + q (residual)
    gemm_ca<128, true><<<g1, 256, smem128>>>(patt, Wfc, q, px, DMODEL, DMODEL);

    // LayerNorm -> d_out (this is 'x' for external attention)
    ln_kernel<<<ROWS / 8, 256>>>(gamma, beta, out);

    // xa = x @ Wmk^T  (N=64)
    gemm_ca<64, false><<<dim3(1, ROWS / 128), 256, smem64>>>(out, Wmk, nullptr, pxa,
                                                             DMODEL, SEXT);
    ext_norm_kernel<<<BSZ, 64>>>();

    // out = x + a @ Wmv^T  (K=64)
    gemm_ca<128, true><<<dim3(DMODEL / 128, ROWS / 128), 256, smem128>>>(pa, Wmv, out, out,
                                                                        SEXT, DMODEL);
}